// round 1
// baseline (speedup 1.0000x reference)
#include <cuda_runtime.h>
#include <cuda_bf16.h>
#include <mma.h>
#include <math_constants.h>

using namespace nvcuda;

// Problem constants
#define DMODEL 1024
#define NHEADS 16
#define DHEAD  64
#define NBATCH 2
#define SQ     2048
#define SK     2048
#define MROWS  (NBATCH * SQ)   // 4096

// ---------------------------------------------------------------------------
// Scratch (device globals: no allocation allowed)
// ---------------------------------------------------------------------------
__device__ float g_qh[(size_t)NBATCH * NHEADS * SQ * DHEAD];   // 16 MB, [b,h,q,d]
__device__ float g_kh[(size_t)NBATCH * NHEADS * SK * DHEAD];   // 16 MB
__device__ float g_vh[(size_t)NBATCH * NHEADS * SK * DHEAD];   // 16 MB
__device__ float g_attn[(size_t)NBATCH * SQ * DMODEL];          // 16 MB, [b,q, h*64+d]

// ---------------------------------------------------------------------------
// TF32 wmma GEMM: C[4096,1024] = A[4096,1024] @ W[1024,1024] + bias
// DST: 0 -> g_qh (head-major), 1 -> g_kh, 2 -> g_vh, 3 -> plain row-major `out`
// For DST==3 the A operand is g_attn (param `A` ignored).
// ---------------------------------------------------------------------------
template<int DST>
__global__ __launch_bounds__(256)
void gemm_tf32_kernel(const float* __restrict__ A,
                      const float* __restrict__ W,
                      const float* __restrict__ bias,
                      float* __restrict__ out)
{
    constexpr int BM = 128, BN = 128, BK = 32;
    __shared__ float As[BM][36];     // ld 36 (144B, 16B-multiple)
    __shared__ float Bs[BK][132];    // ld 132 (528B, 16B-multiple)
    __shared__ float stage[8][256];  // per-warp 16x16 epilogue staging

    const float* Ap = (DST == 3) ? g_attn : A;

    const int tid    = threadIdx.x;
    const int wid    = tid >> 5;
    const int lane   = tid & 31;
    const int warp_m = wid >> 1;   // 0..3
    const int warp_n = wid & 1;    // 0..1
    const int m0 = blockIdx.y * BM;
    const int n0 = blockIdx.x * BN;

    wmma::fragment<wmma::accumulator, 16, 16, 8, float> acc[2][4];
#pragma unroll
    for (int i = 0; i < 2; i++)
#pragma unroll
        for (int j = 0; j < 4; j++)
            wmma::fill_fragment(acc[i][j], 0.0f);

    for (int k0 = 0; k0 < DMODEL; k0 += BK) {
        // Load A tile 128x32 (1024 float4s, 4 per thread)
#pragma unroll
        for (int i = 0; i < 4; i++) {
            int idx = tid + i * 256;
            int r = idx >> 3, c4 = idx & 7;
            float4 v = *(const float4*)(Ap + (size_t)(m0 + r) * DMODEL + k0 + c4 * 4);
            *(float4*)(&As[r][c4 * 4]) = v;
        }
        // Load W tile 32x128
#pragma unroll
        for (int i = 0; i < 4; i++) {
            int idx = tid + i * 256;
            int r = idx >> 5, c4 = idx & 31;
            float4 v = *(const float4*)(W + (size_t)(k0 + r) * DMODEL + n0 + c4 * 4);
            *(float4*)(&Bs[r][c4 * 4]) = v;
        }
        __syncthreads();

#pragma unroll
        for (int kf = 0; kf < 4; kf++) {
            wmma::fragment<wmma::matrix_a, 16, 16, 8, wmma::precision::tf32, wmma::row_major> a[2];
            wmma::fragment<wmma::matrix_b, 16, 16, 8, wmma::precision::tf32, wmma::row_major> b[4];
#pragma unroll
            for (int i = 0; i < 2; i++) {
                wmma::load_matrix_sync(a[i], &As[warp_m * 32 + i * 16][kf * 8], 36);
#pragma unroll
                for (int t = 0; t < a[i].num_elements; t++)
                    a[i].x[t] = wmma::__float_to_tf32(a[i].x[t]);
            }
#pragma unroll
            for (int j = 0; j < 4; j++) {
                wmma::load_matrix_sync(b[j], &Bs[kf * 8][warp_n * 64 + j * 16], 132);
#pragma unroll
                for (int t = 0; t < b[j].num_elements; t++)
                    b[j].x[t] = wmma::__float_to_tf32(b[j].x[t]);
            }
#pragma unroll
            for (int i = 0; i < 2; i++)
#pragma unroll
                for (int j = 0; j < 4; j++)
                    wmma::mma_sync(acc[i][j], a[i], b[j], acc[i][j]);
        }
        __syncthreads();
    }

    // Epilogue: stage each 16x16 frag in smem, add bias, scatter to output
#pragma unroll
    for (int i = 0; i < 2; i++) {
#pragma unroll
        for (int j = 0; j < 4; j++) {
            wmma::store_matrix_sync(&stage[wid][0], acc[i][j], 16, wmma::mem_row_major);
            __syncwarp();
            int grow0 = m0 + warp_m * 32 + i * 16;
            int gcol0 = n0 + warp_n * 64 + j * 16;
#pragma unroll
            for (int t = lane; t < 256; t += 32) {
                int r = t >> 4, c = t & 15;
                int grow = grow0 + r;
                int gcol = gcol0 + c;
                float v = stage[wid][t] + bias[gcol];
                if (DST <= 2) {
                    // head-major: [b, h, row, d]
                    int b_  = grow >> 11;          // /2048
                    int qr  = grow & 2047;
                    int h_  = gcol >> 6;           // /64
                    int d_  = gcol & 63;
                    size_t addr = (((size_t)(b_ * NHEADS + h_) * SQ) + qr) * DHEAD + d_;
                    if (DST == 0) g_qh[addr] = v;
                    else if (DST == 1) g_kh[addr] = v;
                    else g_vh[addr] = v;
                } else {
                    out[(size_t)grow * DMODEL + gcol] = v;
                }
            }
            __syncwarp();
        }
    }
}

// ---------------------------------------------------------------------------
// Flash attention: one CTA per (b, h, 64-query tile). TF32 wmma for QK^T / PV,
// online softmax in fp32. Writes merged layout [b, q, h*64+d] into g_attn.
// ---------------------------------------------------------------------------
#define FL_LD 68   // 68*4 = 272 bytes = 17*16, 16B-multiple

__global__ __launch_bounds__(128)
void flash_attn_kernel()
{
    extern __shared__ float sm[];
    float* Qs = sm;                 // 64 x FL_LD
    float* Ks = Qs + 64 * FL_LD;
    float* Vs = Ks + 64 * FL_LD;
    float* Ss = Vs + 64 * FL_LD;
    float* Os = Ss + 64 * FL_LD;

    const int q0  = blockIdx.x * 64;
    const int h   = blockIdx.y;
    const int b   = blockIdx.z;
    const int tid = threadIdx.x;
    const int wid = tid >> 5;
    const int lane = tid & 31;

    const float* Qg = g_qh + (((size_t)(b * NHEADS + h) * SQ) + q0) * DHEAD;
    const float* Kg = g_kh + ((size_t)(b * NHEADS + h) * SK) * DHEAD;
    const float* Vg = g_vh + ((size_t)(b * NHEADS + h) * SK) * DHEAD;

    // Load Q tile + zero O accumulator
    for (int i = tid; i < 64 * 16; i += 128) {
        int r = i >> 4, c4 = i & 15;
        *(float4*)(Qs + r * FL_LD + c4 * 4) = *(const float4*)(Qg + (size_t)r * DHEAD + c4 * 4);
        float4 z = make_float4(0.f, 0.f, 0.f, 0.f);
        *(float4*)(Os + r * FL_LD + c4 * 4) = z;
    }

    const int rloc = lane >> 1;         // 0..15 (row within warp strip)
    const int half = lane & 1;          // which 32-col half
    const int row  = wid * 16 + rloc;   // 0..63
    float* Srow = Ss + row * FL_LD + half * 32;
    float* Orow = Os + row * FL_LD + half * 32;

    float m_i = -CUDART_INF_F;
    float l_i = 0.0f;

    __syncthreads();

    for (int j = 0; j < SK; j += 64) {
        // Load K,V tiles (64x64 each)
        for (int i = tid; i < 64 * 16; i += 128) {
            int r = i >> 4, c4 = i & 15;
            *(float4*)(Ks + r * FL_LD + c4 * 4) =
                *(const float4*)(Kg + (size_t)(j + r) * DHEAD + c4 * 4);
            *(float4*)(Vs + r * FL_LD + c4 * 4) =
                *(const float4*)(Vg + (size_t)(j + r) * DHEAD + c4 * 4);
        }
        __syncthreads();

        // S = (Q K^T) * scale — warp computes its 16-row strip, all 64 cols
        {
            const int r0 = wid * 16;
#pragma unroll
            for (int n0 = 0; n0 < 64; n0 += 16) {
                wmma::fragment<wmma::accumulator, 16, 16, 8, float> c;
                wmma::fill_fragment(c, 0.0f);
#pragma unroll
                for (int k0 = 0; k0 < 64; k0 += 8) {
                    wmma::fragment<wmma::matrix_a, 16, 16, 8, wmma::precision::tf32, wmma::row_major> a;
                    wmma::fragment<wmma::matrix_b, 16, 16, 8, wmma::precision::tf32, wmma::col_major> bf;
                    wmma::load_matrix_sync(a, Qs + r0 * FL_LD + k0, FL_LD);
                    // K^T via col_major view of row-major K tile
                    wmma::load_matrix_sync(bf, Ks + n0 * FL_LD + k0, FL_LD);
#pragma unroll
                    for (int t = 0; t < a.num_elements; t++) a.x[t] = wmma::__float_to_tf32(a.x[t]);
#pragma unroll
                    for (int t = 0; t < bf.num_elements; t++) bf.x[t] = wmma::__float_to_tf32(bf.x[t]);
                    wmma::mma_sync(c, a, bf, c);
                }
#pragma unroll
                for (int t = 0; t < c.num_elements; t++) c.x[t] *= 0.125f;  // 1/sqrt(64)
                wmma::store_matrix_sync(Ss + r0 * FL_LD + n0, c, FL_LD, wmma::mem_row_major);
            }
        }
        __syncwarp();

        // Online softmax over this warp's 16 rows (2 lanes per row)
        {
            float sv[32];
            float mx = -CUDART_INF_F;
#pragma unroll
            for (int i = 0; i < 32; i++) { sv[i] = Srow[i]; mx = fmaxf(mx, sv[i]); }
            mx = fmaxf(mx, __shfl_xor_sync(0xffffffffu, mx, 1));
            float m_new = fmaxf(m_i, mx);
            float alpha = __expf(m_i - m_new);
            float s = 0.0f;
#pragma unroll
            for (int i = 0; i < 32; i++) {
                float p = __expf(sv[i] - m_new);
                Srow[i] = p;
                s += p;
            }
            s += __shfl_xor_sync(0xffffffffu, s, 1);
            l_i = l_i * alpha + s;
            m_i = m_new;
#pragma unroll
            for (int i = 0; i < 32; i++) Orow[i] *= alpha;
        }
        __syncwarp();

        // O += P @ V
        {
            const int r0 = wid * 16;
#pragma unroll
            for (int n0 = 0; n0 < 64; n0 += 16) {
                wmma::fragment<wmma::accumulator, 16, 16, 8, float> c;
                wmma::load_matrix_sync(c, Os + r0 * FL_LD + n0, FL_LD, wmma::mem_row_major);
#pragma unroll
                for (int k0 = 0; k0 < 64; k0 += 8) {
                    wmma::fragment<wmma::matrix_a, 16, 16, 8, wmma::precision::tf32, wmma::row_major> a;
                    wmma::fragment<wmma::matrix_b, 16, 16, 8, wmma::precision::tf32, wmma::row_major> bf;
                    wmma::load_matrix_sync(a, Ss + r0 * FL_LD + k0, FL_LD);
                    wmma::load_matrix_sync(bf, Vs + k0 * FL_LD + n0, FL_LD);
#pragma unroll
                    for (int t = 0; t < a.num_elements; t++) a.x[t] = wmma::__float_to_tf32(a.x[t]);
#pragma unroll
                    for (int t = 0; t < bf.num_elements; t++) bf.x[t] = wmma::__float_to_tf32(bf.x[t]);
                    wmma::mma_sync(c, a, bf, c);
                }
                wmma::store_matrix_sync(Os + r0 * FL_LD + n0, c, FL_LD, wmma::mem_row_major);
            }
        }
        __syncthreads();   // protect Ks/Vs/Ss reuse next iteration
    }

    // Normalize and write merged layout [b, q, h*64 + d]
    float inv_l = 1.0f / l_i;
    float* og = g_attn + ((size_t)(b * SQ + q0 + row) * DMODEL) + h * DHEAD + half * 32;
#pragma unroll
    for (int i = 0; i < 32; i++) og[i] = Orow[i] * inv_l;
}

// ---------------------------------------------------------------------------
// Launch
// ---------------------------------------------------------------------------
extern "C" void kernel_launch(void* const* d_in, const int* in_sizes, int n_in,
                              void* d_out, int out_size)
{
    const float* q  = (const float*)d_in[0];
    const float* k  = (const float*)d_in[1];
    const float* v  = (const float*)d_in[2];
    const float* Wq = (const float*)d_in[3];
    const float* bq = (const float*)d_in[4];
    const float* Wk = (const float*)d_in[5];
    const float* bk = (const float*)d_in[6];
    const float* Wv = (const float*)d_in[7];
    const float* bv = (const float*)d_in[8];
    const float* Wo = (const float*)d_in[9];
    const float* bo = (const float*)d_in[10];
    float* out = (float*)d_out;

    dim3 gblock(256);
    dim3 ggrid(DMODEL / 128, MROWS / 128);   // (8, 32)

    // Projections -> head-major scratch
    gemm_tf32_kernel<0><<<ggrid, gblock>>>(q, Wq, bq, nullptr);
    gemm_tf32_kernel<1><<<ggrid, gblock>>>(k, Wk, bk, nullptr);
    gemm_tf32_kernel<2><<<ggrid, gblock>>>(v, Wv, bv, nullptr);

    // Flash attention
    const int flash_smem = 5 * 64 * FL_LD * (int)sizeof(float);  // 87,040 B
    cudaFuncSetAttribute(flash_attn_kernel,
                         cudaFuncAttributeMaxDynamicSharedMemorySize, flash_smem);
    dim3 fgrid(SQ / 64, NHEADS, NBATCH);     // (32, 16, 2)
    flash_attn_kernel<<<fgrid, 128, flash_smem>>>();

    // Output projection (reads g_attn internally)
    gemm_tf32_kernel<3><<<ggrid, gblock>>>(nullptr, Wo, bo, out);
}